// round 1
// baseline (speedup 1.0000x reference)
#include <cuda_runtime.h>

#define HH 512
#define WW 512
#define CC 3
#define NB 4
#define ITERS 30
#define TILE 32
#define LATW (TILE + 4)   // 36: halo 2 for the chained 3x3+3x3 stencil
#define RBW  (TILE + 2)   // 34: intermediate (relative_blur) region
#define NELEM (NB * HH * WW * CC)

__device__ float  g_buf0[NELEM];
__device__ float  g_buf1[NELEM];
__device__ double g_sums[ITERS];

__device__ __forceinline__ int refl(int i, int n) {
    // jnp/np "reflect" (mirror without edge duplication): -1 -> 1, n -> n-2
    if (i < 0) i = -i;
    if (i >= n) i = 2 * n - 2 - i;
    return i;
}

__global__ void zero_sums_kernel() {
    if (threadIdx.x < ITERS) g_sums[threadIdx.x] = 0.0;
}

__global__ __launch_bounds__(256) void rl_iter_kernel(
    const float* __restrict__ latent_in,
    const float* __restrict__ inputs,
    const float* __restrict__ k1,   // kernel          (3,3,1,3) -> idx = (dy*3+dx)*3 + ch
    const float* __restrict__ k2,   // kernel_flipped  (3,3,1,3)
    float* __restrict__ latent_out,
    int iter)
{
    __shared__ float s_lat[LATW][LATW][CC];
    __shared__ float s_in [RBW][RBW][CC];
    __shared__ float s_rb [RBW][RBW][CC];
    __shared__ float s_k1[27];
    __shared__ float s_k2[27];
    __shared__ int    s_done;
    __shared__ double s_red[8];

    const int tid = threadIdx.x;
    const int n  = blockIdx.z;
    const int r0 = blockIdx.y * TILE;
    const int c0 = blockIdx.x * TILE;

    // --- early-freeze flag: OR over all previous iterations' diffs ---
    if (tid == 0) {
        int done = 0;
        for (int j = 0; j < iter; j++) {
            double diff = fabs(1.0 - g_sums[j] * (1.0 / (double)NELEM));
            if (diff < 1e-5) done = 1;
        }
        s_done = done;
    }
    if (tid < 27) { s_k1[tid] = k1[tid]; s_k2[tid] = k2[tid]; }
    __syncthreads();

    const float* lat_img = latent_in  + (size_t)n * HH * WW * CC;
    float*       out_img = latent_out + (size_t)n * HH * WW * CC;

    if (s_done) {
        // latent is frozen: just propagate it through the ping-pong chain
        #pragma unroll 4
        for (int i = tid; i < TILE * TILE * CC; i += 256) {
            int y  = i / (TILE * CC);
            int cc = i - y * (TILE * CC);
            size_t addr = ((size_t)(r0 + y) * WW + c0) * CC + cc;
            out_img[addr] = lat_img[addr];
        }
        return;
    }

    const float* in_img = inputs + (size_t)n * HH * WW * CC;

    // --- load latent tile with halo 2 (reflect) ---
    for (int i = tid; i < LATW * LATW * CC; i += 256) {
        int row = i / (LATW * CC);
        int cc  = i - row * (LATW * CC);
        int col = cc / CC;
        int ch  = cc - col * CC;
        int gr = refl(r0 - 2 + row, HH);
        int gc = refl(c0 - 2 + col, WW);
        s_lat[row][col][ch] = lat_img[((size_t)gr * WW + gc) * CC + ch];
    }
    // --- load inputs tile with halo 1 (reflect) ---
    for (int i = tid; i < RBW * RBW * CC; i += 256) {
        int row = i / (RBW * CC);
        int cc  = i - row * (RBW * CC);
        int col = cc / CC;
        int ch  = cc - col * CC;
        int gr = refl(r0 - 1 + row, HH);
        int gc = refl(c0 - 1 + col, WW);
        s_in[row][col][ch] = in_img[((size_t)gr * WW + gc) * CC + ch];
    }
    __syncthreads();

    // --- stage 1: est_conv = conv(latent, k1); rb = inputs / est_conv  (34x34 region) ---
    for (int i = tid; i < RBW * RBW; i += 256) {
        int y = i / RBW;
        int x = i - y * RBW;
        #pragma unroll
        for (int ch = 0; ch < CC; ch++) {
            float acc = 0.f;
            #pragma unroll
            for (int dy = 0; dy < 3; dy++)
                #pragma unroll
                for (int dx = 0; dx < 3; dx++)
                    acc = fmaf(s_lat[y + dy][x + dx][ch], s_k1[(dy * 3 + dx) * 3 + ch], acc);
            s_rb[y][x][ch] = s_in[y][x][ch] / acc;
        }
    }
    __syncthreads();

    // --- stage 2: error_est = conv(rb, k2); new_latent = latent * error_est  (32x32) ---
    double lsum = 0.0;
    #pragma unroll 4
    for (int i = tid; i < TILE * TILE; i += 256) {
        int y = i / TILE;
        int x = i - y * TILE;
        size_t addr = ((size_t)(r0 + y) * WW + (c0 + x)) * CC;
        #pragma unroll
        for (int ch = 0; ch < CC; ch++) {
            float e = 0.f;
            #pragma unroll
            for (int dy = 0; dy < 3; dy++)
                #pragma unroll
                for (int dx = 0; dx < 3; dx++)
                    e = fmaf(s_rb[y + dy][x + dx][ch], s_k2[(dy * 3 + dx) * 3 + ch], e);
            lsum += (double)e;
            out_img[addr + ch] = s_lat[y + 2][x + 2][ch] * e;
        }
    }

    // --- block reduce lsum (double), accumulate into g_sums[iter] ---
    int lane = tid & 31;
    int warp = tid >> 5;
    #pragma unroll
    for (int off = 16; off > 0; off >>= 1)
        lsum += __shfl_down_sync(0xffffffffu, lsum, off);
    if (lane == 0) s_red[warp] = lsum;
    __syncthreads();
    if (warp == 0) {
        double v = (lane < 8) ? s_red[lane] : 0.0;
        #pragma unroll
        for (int off = 4; off > 0; off >>= 1)
            v += __shfl_down_sync(0xffffffffu, v, off);
        if (lane == 0) atomicAdd(&g_sums[iter], v);
    }
}

extern "C" void kernel_launch(void* const* d_in, const int* in_sizes, int n_in,
                              void* d_out, int out_size) {
    const float* inputs = (const float*)d_in[0];
    const float* k1     = (const float*)d_in[1];  // kernel
    const float* k2     = (const float*)d_in[2];  // kernel_flipped
    float* out = (float*)d_out;

    float *b0 = nullptr, *b1 = nullptr;
    cudaGetSymbolAddress((void**)&b0, g_buf0);
    cudaGetSymbolAddress((void**)&b1, g_buf1);

    zero_sums_kernel<<<1, 32>>>();

    dim3 grid(WW / TILE, HH / TILE, NB);
    const float* cur = inputs;
    for (int it = 0; it < ITERS; it++) {
        float* nxt = (it == ITERS - 1) ? out : ((it & 1) ? b1 : b0);
        rl_iter_kernel<<<grid, 256>>>(cur, inputs, k1, k2, nxt, it);
        cur = nxt;
    }
}

// round 2
// speedup vs baseline: 1.6660x; 1.6660x over previous
#include <cuda_runtime.h>

#define HH 512
#define WW 512
#define CC 3
#define NB 4
#define ITERS 30
#define TILE 32
#define NELEM (NB * HH * WW * CC)

__device__ float  g_buf0[NELEM];
__device__ float  g_buf1[NELEM];
__device__ double g_sums[ITERS];

__device__ __forceinline__ int refl(int i, int n) {
    // np "reflect": -1 -> 1, n -> n-2
    if (i < 0) i = -i;
    if (i >= n) i = 2 * n - 2 - i;
    return i;
}

__global__ void zero_sums_kernel() {
    if (threadIdx.x < ITERS) g_sums[threadIdx.x] = 0.0;
}

// block: (32, 8); tile 32x32 output pixels
// s_lat: 36x36 pixels x3ch (halo 2), s_rb: 34x34 x3ch (halo 1)
__global__ __launch_bounds__(256, 6) void rl_iter_kernel(
    const float* __restrict__ latent_in,
    const float* __restrict__ inputs,
    const float* __restrict__ k1g,
    const float* __restrict__ k2g,
    float* __restrict__ latent_out,
    int iter)
{
    __shared__ float  s_lat[36][108];
    __shared__ float  s_rb [34][102];
    __shared__ float  s_k[54];          // [0:27) k1, [27:54) k2, layout (dy*3+dx)*3+ch
    __shared__ double s_red[8];
    __shared__ int    s_done;

    const int tx  = threadIdx.x;
    const int ty  = threadIdx.y;
    const int tid = ty * 32 + tx;
    const int n   = blockIdx.z;
    const int r0  = blockIdx.y * TILE;
    const int c0  = blockIdx.x * TILE;

    if (tid == 0) {
        int done = 0;
        for (int j = 0; j < iter; j++) {
            double d = fabs(1.0 - g_sums[j] * (1.0 / (double)NELEM));
            if (d < 1e-5) done = 1;
        }
        s_done = done;
    }
    if (tid < 54) s_k[tid] = (tid < 27) ? k1g[tid] : k2g[tid - 27];
    __syncthreads();

    const float* lat_img = latent_in  + (size_t)n * HH * WW * CC;
    float*       out_img = latent_out + (size_t)n * HH * WW * CC;

    if (s_done) {  // frozen: propagate latent through the ping-pong chain
        for (int y = ty; y < TILE; y += 8) {
            size_t base = ((size_t)(r0 + y) * WW + c0) * CC;
            for (int f = tx; f < TILE * CC; f += 32)
                out_img[base + f] = lat_img[base + f];
        }
        return;
    }

    const float* in_img = inputs + (size_t)n * HH * WW * CC;

    // ---- load latent 36 rows x 108 floats (reflect halo 2) ----
    const bool xin2 = (c0 >= 2) && (c0 <= WW - TILE - 2);
    for (int r = ty; r < 36; r += 8) {
        int gr = refl(r0 - 2 + r, HH);
        const float* rp = lat_img + (size_t)gr * (WW * CC);
        if (xin2) {
            const float* p = rp + (c0 - 2) * CC;
            s_lat[r][tx]      = p[tx];
            s_lat[r][tx + 32] = p[tx + 32];
            s_lat[r][tx + 64] = p[tx + 64];
            if (tx < 12) s_lat[r][tx + 96] = p[tx + 96];
        } else {
            for (int f = tx; f < 108; f += 32) {
                int col = f / 3, ch = f - 3 * col;
                int gc = refl(c0 - 2 + col, WW);
                s_lat[r][f] = rp[gc * CC + ch];
            }
        }
    }
    __syncthreads();

    const bool xin1 = (c0 >= 1) && (c0 <= WW - TILE - 1);

    // ---- stage 1: est = conv(lat,k1); rb = in/est over 34x34 region ----
    if (ty < 7) {
        // warp ty handles rb rows [ty*5, min(ty*5+5,34)), column x = tx
        const int y0   = ty * 5;
        const int yend = min(y0 + 5, 34);
        #pragma unroll
        for (int ch = 0; ch < 3; ch++) {
            const float kk0 = s_k[ch],      kk1 = s_k[3 + ch],  kk2 = s_k[6 + ch];
            const float kk3 = s_k[9 + ch],  kk4 = s_k[12 + ch], kk5 = s_k[15 + ch];
            const float kk6 = s_k[18 + ch], kk7 = s_k[21 + ch], kk8 = s_k[24 + ch];
            const int xc = tx * 3 + ch;
            float a0 = s_lat[y0][xc],     a1 = s_lat[y0][xc + 3],     a2 = s_lat[y0][xc + 6];
            float b0 = s_lat[y0 + 1][xc], b1 = s_lat[y0 + 1][xc + 3], b2 = s_lat[y0 + 1][xc + 6];
            for (int y = y0; y < yend; y++) {
                float v0 = s_lat[y + 2][xc], v1 = s_lat[y + 2][xc + 3], v2 = s_lat[y + 2][xc + 6];
                float est = a0 * kk0;
                est = fmaf(a1, kk1, est); est = fmaf(a2, kk2, est);
                est = fmaf(b0, kk3, est); est = fmaf(b1, kk4, est);
                est = fmaf(b2, kk5, est); est = fmaf(v0, kk6, est);
                est = fmaf(v1, kk7, est); est = fmaf(v2, kk8, est);
                int gy = refl(r0 - 1 + y, HH);
                float inp;
                if (xin1) {
                    inp = __ldg(in_img + ((size_t)gy * WW + (c0 - 1 + tx)) * CC + ch);
                } else {
                    int gx = refl(c0 - 1 + tx, WW);
                    inp = __ldg(in_img + ((size_t)gy * WW + gx) * CC + ch);
                }
                s_rb[y][xc] = __fdividef(inp, est);
                a0 = b0; a1 = b1; a2 = b2;
                b0 = v0; b1 = v1; b2 = v2;
            }
        }
    } else {
        // warp 7: rb columns x = 32,33 for all 34 rows (no rolling; tiny)
        for (int idx = tx; idx < 68; idx += 32) {
            int x = 32 + (idx & 1);
            int y = idx >> 1;
            int gy = refl(r0 - 1 + y, HH);
            int gx = xin1 ? (c0 - 1 + x) : refl(c0 - 1 + x, WW);
            const float* ip = in_img + ((size_t)gy * WW + gx) * CC;
            int xc = x * 3;
            #pragma unroll
            for (int ch = 0; ch < 3; ch++) {
                float est = 0.f;
                #pragma unroll
                for (int dy = 0; dy < 3; dy++)
                    #pragma unroll
                    for (int dx = 0; dx < 3; dx++)
                        est = fmaf(s_lat[y + dy][xc + dx * 3 + ch],
                                   s_k[(dy * 3 + dx) * 3 + ch], est);
                s_rb[y][xc + ch] = __fdividef(__ldg(ip + ch), est);
            }
        }
    }
    __syncthreads();

    // ---- stage 2: e = conv(rb,k2); out = lat*e over 32x32 ----
    float fsum = 0.f;
    {
        const int y0 = ty * 4;
        #pragma unroll
        for (int ch = 0; ch < 3; ch++) {
            const float kk0 = s_k[27 + ch], kk1 = s_k[30 + ch], kk2 = s_k[33 + ch];
            const float kk3 = s_k[36 + ch], kk4 = s_k[39 + ch], kk5 = s_k[42 + ch];
            const float kk6 = s_k[45 + ch], kk7 = s_k[48 + ch], kk8 = s_k[51 + ch];
            const int xc = tx * 3 + ch;
            float a0 = s_rb[y0][xc],     a1 = s_rb[y0][xc + 3],     a2 = s_rb[y0][xc + 6];
            float b0 = s_rb[y0 + 1][xc], b1 = s_rb[y0 + 1][xc + 3], b2 = s_rb[y0 + 1][xc + 6];
            #pragma unroll
            for (int k = 0; k < 4; k++) {
                int y = y0 + k;
                float v0 = s_rb[y + 2][xc], v1 = s_rb[y + 2][xc + 3], v2 = s_rb[y + 2][xc + 6];
                float e = a0 * kk0;
                e = fmaf(a1, kk1, e); e = fmaf(a2, kk2, e);
                e = fmaf(b0, kk3, e); e = fmaf(b1, kk4, e);
                e = fmaf(b2, kk5, e); e = fmaf(v0, kk6, e);
                e = fmaf(v1, kk7, e); e = fmaf(v2, kk8, e);
                fsum += e;
                float lat = s_lat[y + 2][(tx + 2) * 3 + ch];
                out_img[((size_t)(r0 + y) * WW + (c0 + tx)) * CC + ch] = lat * e;
                a0 = b0; a1 = b1; a2 = b2;
                b0 = v0; b1 = v1; b2 = v2;
            }
        }
    }

    // ---- block reduction: fp32 warp-reduce, double block total, one atomic ----
    #pragma unroll
    for (int off = 16; off > 0; off >>= 1)
        fsum += __shfl_down_sync(0xffffffffu, fsum, off);
    if (tx == 0) s_red[ty] = (double)fsum;
    __syncthreads();
    if (tid == 0) {
        double v = 0.0;
        #pragma unroll
        for (int i = 0; i < 8; i++) v += s_red[i];
        atomicAdd(&g_sums[iter], v);
    }
}

extern "C" void kernel_launch(void* const* d_in, const int* in_sizes, int n_in,
                              void* d_out, int out_size) {
    const float* inputs = (const float*)d_in[0];
    const float* k1     = (const float*)d_in[1];
    const float* k2     = (const float*)d_in[2];
    float* out = (float*)d_out;

    float *b0 = nullptr, *b1 = nullptr;
    cudaGetSymbolAddress((void**)&b0, g_buf0);
    cudaGetSymbolAddress((void**)&b1, g_buf1);

    zero_sums_kernel<<<1, 32>>>();

    dim3 blk(32, 8, 1);
    dim3 grid(WW / TILE, HH / TILE, NB);
    const float* cur = inputs;
    for (int it = 0; it < ITERS; it++) {
        float* nxt = (it == ITERS - 1) ? out : ((it & 1) ? b1 : b0);
        rl_iter_kernel<<<grid, blk>>>(cur, inputs, k1, k2, nxt, it);
        cur = nxt;
    }
}

// round 3
// speedup vs baseline: 1.9568x; 1.1745x over previous
#include <cuda_runtime.h>

#define HH 512
#define WW 512
#define CC 3
#define NB 4
#define ITERS 30
#define TILE 32
#define NELEM (NB * HH * WW * CC)

__device__ float  g_buf0[NELEM];
__device__ float  g_buf1[NELEM];
__device__ double g_sums[ITERS];

__device__ __forceinline__ int refl(int i, int n) {
    // np "reflect": -1 -> 1, n -> n-2
    if (i < 0) i = -i;
    if (i >= n) i = 2 * n - 2 - i;
    return i;
}

__global__ void zero_sums_kernel() {
    if (threadIdx.x < ITERS) g_sums[threadIdx.x] = 0.0;
}

// block: (32, 8); tile 32x32 output pixels
// s_lat: 36x36 pixels x3ch (halo 2), s_rb: 34x34 x3ch (halo 1)
// 7 blocks/SM * 148 SMs = 1036 >= 1024 blocks -> entire grid is ONE wave.
__global__ __launch_bounds__(256, 7) void rl_iter_kernel(
    const float* __restrict__ latent_in,
    const float* __restrict__ inputs,
    const float* __restrict__ k1g,
    const float* __restrict__ k2g,
    float* __restrict__ latent_out,
    int iter)
{
    __shared__ float  s_lat[36][108];
    __shared__ float  s_rb [34][102];
    __shared__ float  s_k[54];          // [0:27) k1, [27:54) k2, layout (dy*3+dx)*3+ch
    __shared__ double s_red[8];
    __shared__ int    s_done;

    const int tx  = threadIdx.x;
    const int ty  = threadIdx.y;
    const int tid = ty * 32 + tx;
    const int n   = blockIdx.z;
    const int r0  = blockIdx.y * TILE;
    const int c0  = blockIdx.x * TILE;

    if (tid == 0) {
        int done = 0;
        for (int j = 0; j < iter; j++) {
            double d = fabs(1.0 - g_sums[j] * (1.0 / (double)NELEM));
            if (d < 1e-5) done = 1;
        }
        s_done = done;
    }
    if (tid < 54) s_k[tid] = (tid < 27) ? k1g[tid] : k2g[tid - 27];
    __syncthreads();

    const float* lat_img = latent_in  + (size_t)n * (HH * WW * CC);
    float*       out_img = latent_out + (size_t)n * (HH * WW * CC);

    if (s_done) {  // frozen: propagate latent through the ping-pong chain
        for (int y = ty; y < TILE; y += 8) {
            size_t base = ((size_t)(r0 + y) * WW + c0) * CC;
            for (int f = tx; f < TILE * CC; f += 32)
                out_img[base + f] = lat_img[base + f];
        }
        return;
    }

    const float* in_img = inputs + (size_t)n * (HH * WW * CC);

    // ---- load latent 36 rows x 108 floats (reflect halo 2) ----
    const bool xin2 = (c0 >= 2) && (c0 <= WW - TILE - 2);
    for (int r = ty; r < 36; r += 8) {
        int gr = refl(r0 - 2 + r, HH);
        const float* rp = lat_img + (size_t)gr * (WW * CC);
        if (xin2) {
            const float* p = rp + (c0 - 2) * CC;
            s_lat[r][tx]      = p[tx];
            s_lat[r][tx + 32] = p[tx + 32];
            s_lat[r][tx + 64] = p[tx + 64];
            if (tx < 12) s_lat[r][tx + 96] = p[tx + 96];
        } else {
            for (int f = tx; f < 108; f += 32) {
                int col = f / 3, ch = f - 3 * col;
                int gc = refl(c0 - 2 + col, WW);
                s_lat[r][f] = rp[gc * CC + ch];
            }
        }
    }
    __syncthreads();

    const bool xin1 = (c0 >= 1) && (c0 <= WW - TILE - 1);

    // ---- stage 1: est = conv(lat,k1); rb = in/est over 34x34 region ----
    if (ty < 7) {
        // warp ty handles rb rows [ty*5, min(ty*5+5,34)), column x = tx
        const int y0   = ty * 5;
        const int yend = min(y0 + 5, 34);
        #pragma unroll
        for (int ch = 0; ch < 3; ch++) {
            const float kk0 = s_k[ch],      kk1 = s_k[3 + ch],  kk2 = s_k[6 + ch];
            const float kk3 = s_k[9 + ch],  kk4 = s_k[12 + ch], kk5 = s_k[15 + ch];
            const float kk6 = s_k[18 + ch], kk7 = s_k[21 + ch], kk8 = s_k[24 + ch];
            const int xc = tx * 3 + ch;
            float a0 = s_lat[y0][xc],     a1 = s_lat[y0][xc + 3],     a2 = s_lat[y0][xc + 6];
            float b0 = s_lat[y0 + 1][xc], b1 = s_lat[y0 + 1][xc + 3], b2 = s_lat[y0 + 1][xc + 6];
            for (int y = y0; y < yend; y++) {
                float v0 = s_lat[y + 2][xc], v1 = s_lat[y + 2][xc + 3], v2 = s_lat[y + 2][xc + 6];
                float est = a0 * kk0;
                est = fmaf(a1, kk1, est); est = fmaf(a2, kk2, est);
                est = fmaf(b0, kk3, est); est = fmaf(b1, kk4, est);
                est = fmaf(b2, kk5, est); est = fmaf(v0, kk6, est);
                est = fmaf(v1, kk7, est); est = fmaf(v2, kk8, est);
                int gy = refl(r0 - 1 + y, HH);
                int gx = xin1 ? (c0 - 1 + tx) : refl(c0 - 1 + tx, WW);
                float inp = __ldg(in_img + ((size_t)gy * WW + gx) * CC + ch);
                s_rb[y][xc] = __fdividef(inp, est);
                a0 = b0; a1 = b1; a2 = b2;
                b0 = v0; b1 = v1; b2 = v2;
            }
        }
    } else {
        // warp 7: rb columns x = 32,33 for all 34 rows
        for (int idx = tx; idx < 68; idx += 32) {
            int x = 32 + (idx & 1);
            int y = idx >> 1;
            int gy = refl(r0 - 1 + y, HH);
            int gx = xin1 ? (c0 - 1 + x) : refl(c0 - 1 + x, WW);
            const float* ip = in_img + ((size_t)gy * WW + gx) * CC;
            int xc = x * 3;
            #pragma unroll
            for (int ch = 0; ch < 3; ch++) {
                float est = 0.f;
                #pragma unroll
                for (int dy = 0; dy < 3; dy++)
                    #pragma unroll
                    for (int dx = 0; dx < 3; dx++)
                        est = fmaf(s_lat[y + dy][xc + dx * 3 + ch],
                                   s_k[(dy * 3 + dx) * 3 + ch], est);
                s_rb[y][xc + ch] = __fdividef(__ldg(ip + ch), est);
            }
        }
    }
    __syncthreads();

    // ---- stage 2: e = conv(rb,k2); out = lat*e over 32x32 ----
    float fsum = 0.f;
    {
        const int y0 = ty * 4;
        #pragma unroll
        for (int ch = 0; ch < 3; ch++) {
            const float kk0 = s_k[27 + ch], kk1 = s_k[30 + ch], kk2 = s_k[33 + ch];
            const float kk3 = s_k[36 + ch], kk4 = s_k[39 + ch], kk5 = s_k[42 + ch];
            const float kk6 = s_k[45 + ch], kk7 = s_k[48 + ch], kk8 = s_k[51 + ch];
            const int xc = tx * 3 + ch;
            float a0 = s_rb[y0][xc],     a1 = s_rb[y0][xc + 3],     a2 = s_rb[y0][xc + 6];
            float b0 = s_rb[y0 + 1][xc], b1 = s_rb[y0 + 1][xc + 3], b2 = s_rb[y0 + 1][xc + 6];
            #pragma unroll
            for (int k = 0; k < 4; k++) {
                int y = y0 + k;
                float v0 = s_rb[y + 2][xc], v1 = s_rb[y + 2][xc + 3], v2 = s_rb[y + 2][xc + 6];
                float e = a0 * kk0;
                e = fmaf(a1, kk1, e); e = fmaf(a2, kk2, e);
                e = fmaf(b0, kk3, e); e = fmaf(b1, kk4, e);
                e = fmaf(b2, kk5, e); e = fmaf(v0, kk6, e);
                e = fmaf(v1, kk7, e); e = fmaf(v2, kk8, e);
                fsum += e;
                float lat = s_lat[y + 2][(tx + 2) * 3 + ch];
                out_img[((size_t)(r0 + y) * WW + (c0 + tx)) * CC + ch] = lat * e;
                a0 = b0; a1 = b1; a2 = b2;
                b0 = v0; b1 = v1; b2 = v2;
            }
        }
    }

    // ---- block reduction: fp32 warp-reduce, double block total, one atomic ----
    #pragma unroll
    for (int off = 16; off > 0; off >>= 1)
        fsum += __shfl_down_sync(0xffffffffu, fsum, off);
    if (tx == 0) s_red[ty] = (double)fsum;
    __syncthreads();
    if (tid == 0) {
        double v = 0.0;
        #pragma unroll
        for (int i = 0; i < 8; i++) v += s_red[i];
        atomicAdd(&g_sums[iter], v);
    }
}

extern "C" void kernel_launch(void* const* d_in, const int* in_sizes, int n_in,
                              void* d_out, int out_size) {
    const float* inputs = (const float*)d_in[0];
    const float* k1     = (const float*)d_in[1];
    const float* k2     = (const float*)d_in[2];
    float* out = (float*)d_out;

    float *b0 = nullptr, *b1 = nullptr;
    cudaGetSymbolAddress((void**)&b0, g_buf0);
    cudaGetSymbolAddress((void**)&b1, g_buf1);

    zero_sums_kernel<<<1, 32>>>();

    dim3 blk(32, 8, 1);
    dim3 grid(WW / TILE, HH / TILE, NB);
    const float* cur = inputs;
    for (int it = 0; it < ITERS; it++) {
        float* nxt = (it == ITERS - 1) ? out : ((it & 1) ? b1 : b0);
        rl_iter_kernel<<<grid, blk>>>(cur, inputs, k1, k2, nxt, it);
        cur = nxt;
    }
}